// round 7
// baseline (speedup 1.0000x reference)
#include <cuda_runtime.h>

// ============================================================================
// STGCNEncoder — fused persistent kernel, v2.
// Only row 0 of the GCN output feeds the GRU.
//  Pass A: stream dst, unsigned-min trick to find dst==0 edges (~1.6 instr/edge)
//  Pass B: u16 presence table in smem -> exact degrees of the ~34-node set
//          (~2.6 instr/edge, rare global atomics on hits)
//  Then encoder GEMVs (block/term) + gh overlap, block-0 tail (g0, gi, gates).
//  3 grid barriers total. B=1024 for 8 warps/SMSP.
// ============================================================================

#define G   148
#define B   1024
#define STR (G * B)
#define CAP 2048

__device__ unsigned long long g_bar;       // monotonic grid-barrier counter
__device__ int   g_cnt;                    // # dst==0 edges (zeroed at end of run)
__device__ int   g_srcs[CAP];
__device__ int   g_nodecnt[CAP + 2];       // per-canonical-node indeg (zeroed at end)
__device__ float g_ybuf[CAP + 1][128];
__device__ float g_gh[768];

extern __shared__ unsigned short sP[];     // presence table, N u16 entries

__device__ __forceinline__ void gbar() {
    __threadfence();
    __syncthreads();
    if (threadIdx.x == 0) {
        unsigned long long t = atomicAdd(&g_bar, 1ULL);
        unsigned long long target = t - (t % G) + G;
        volatile unsigned long long* p = &g_bar;
        while (*p < target) __nanosleep(64);
    }
    __syncthreads();
    __threadfence();
}

__global__ void __launch_bounds__(B, 1) k_fused(
    const float* __restrict__ nf, const float* __restrict__ h,
    const float* __restrict__ W_enc, const float* __restrict__ b_enc,
    const float* __restrict__ W_gcn, const float* __restrict__ b_gcn,
    const float* __restrict__ W_ih, const float* __restrict__ W_hh,
    const float* __restrict__ b_ih, const float* __restrict__ b_hh,
    const unsigned* __restrict__ w, int E, int N, float* __restrict__ out)
{
    __shared__ int   sBad;
    __shared__ float sF[64];
    const int t = threadIdx.x, lane = t & 31, wid = t >> 5;
    const int bid = blockIdx.x;
    const int gid = bid * B + t;

    // zero presence table (16B stores)
    {
        int nw = (N + 7) >> 3;
        uint4* p4 = (uint4*)sP;
        uint4 z = make_uint4(0, 0, 0, 0);
        for (int i = t; i < nw; i += B) p4[i] = z;
    }
    if (t == 0) sBad = 0;
    __syncthreads();
    // dtype detect (per block, no grid barrier): int64 ids<2^31 => odd words 0
    {
        int bad = 0;
        for (int i = t; i < 2048 && i < E; i += B) bad |= (int)w[2 * i + 1];
        if (bad) atomicOr(&sBad, 1);
    }
    __syncthreads();
    const bool is64 = (sBad == 0);

    // ---------------- Pass A: collect srcs of dst==0 edges ----------------
    if (is64) {
        const long long* srcq = (const long long*)w;
        if ((E & 1) == 0) {
            const uint4* dv = (const uint4*)(w + 2L * E);  // dst as pairs of {lo,hi}
            int nv = E >> 1;
            int i = gid;
#define CHK64(v, j) { \
    if ((v).x == 0) { int p = atomicAdd(&g_cnt, 1); if (p < CAP) g_srcs[p] = (int)srcq[2L * (j)]; } \
    if ((v).z == 0) { int p = atomicAdd(&g_cnt, 1); if (p < CAP) g_srcs[p] = (int)srcq[2L * (j) + 1]; } }
            for (; i + 3 * STR < nv; i += 4 * STR) {
                uint4 v0 = dv[i], v1 = dv[i + STR], v2 = dv[i + 2 * STR], v3 = dv[i + 3 * STR];
                unsigned m = min(min(min(v0.x, v0.z), min(v1.x, v1.z)),
                                 min(min(v2.x, v2.z), min(v3.x, v3.z)));
                if (m == 0) { CHK64(v0, i); CHK64(v1, i + STR); CHK64(v2, i + 2 * STR); CHK64(v3, i + 3 * STR); }
            }
            for (; i < nv; i += STR) {
                uint4 v = dv[i];
                if (min(v.x, v.z) == 0) { CHK64(v, i); }
            }
        } else {
            const long long* dst = srcq + E;
            for (long i = gid; i < E; i += STR)
                if (dst[i] == 0) { int p = atomicAdd(&g_cnt, 1); if (p < CAP) g_srcs[p] = (int)srcq[i]; }
        }
    } else {
        const int* srci = (const int*)w;
        if ((E & 3) == 0) {
            const uint4* dv = (const uint4*)(w + E);
            int nv = E >> 2;
            int i = gid;
#define CHK32(v, j) { \
    if ((v).x == 0) { int p = atomicAdd(&g_cnt, 1); if (p < CAP) g_srcs[p] = srci[4L * (j)]; } \
    if ((v).y == 0) { int p = atomicAdd(&g_cnt, 1); if (p < CAP) g_srcs[p] = srci[4L * (j) + 1]; } \
    if ((v).z == 0) { int p = atomicAdd(&g_cnt, 1); if (p < CAP) g_srcs[p] = srci[4L * (j) + 2]; } \
    if ((v).w == 0) { int p = atomicAdd(&g_cnt, 1); if (p < CAP) g_srcs[p] = srci[4L * (j) + 3]; } }
            for (; i + 3 * STR < nv; i += 4 * STR) {
                uint4 v0 = dv[i], v1 = dv[i + STR], v2 = dv[i + 2 * STR], v3 = dv[i + 3 * STR];
                unsigned m = min(min(min(min(v0.x, v0.y), min(v0.z, v0.w)),
                                     min(min(v1.x, v1.y), min(v1.z, v1.w))),
                                 min(min(min(v2.x, v2.y), min(v2.z, v2.w)),
                                     min(min(v3.x, v3.y), min(v3.z, v3.w))));
                if (m == 0) { CHK32(v0, i); CHK32(v1, i + STR); CHK32(v2, i + 2 * STR); CHK32(v3, i + 3 * STR); }
            }
            for (; i < nv; i += STR) {
                uint4 v = dv[i];
                if (min(min(v.x, v.y), min(v.z, v.w)) == 0) { CHK32(v, i); }
            }
        } else {
            const int* dst = srci + E;
            for (long i = gid; i < E; i += STR)
                if (dst[i] == 0) { int p = atomicAdd(&g_cnt, 1); if (p < CAP) g_srcs[p] = srci[i]; }
        }
    }
    gbar();  // -------- barrier 1 --------

    int cnt = g_cnt; if (cnt > CAP) cnt = CAP;
    const int M = cnt + 1;                      // + node-0 self-loop term

    // build presence table (every block, deterministic last-write-wins order)
    if (t == 0) {
        for (int i = 0; i < cnt; i++) sP[g_srcs[i]] = (unsigned short)(i + 1);
        if (sP[0] == 0) sP[0] = (unsigned short)(cnt + 1);
    }
    __syncthreads();

    // ---------------- Pass B: count set-membership over dst ----------------
#define CNT2(v) { unsigned p; p = sP[(v).x]; if (p) atomicAdd(&g_nodecnt[p - 1], 1); \
                              p = sP[(v).z]; if (p) atomicAdd(&g_nodecnt[p - 1], 1); }
#define CNT4(v) { unsigned p; p = sP[(v).x]; if (p) atomicAdd(&g_nodecnt[p - 1], 1); \
                              p = sP[(v).y]; if (p) atomicAdd(&g_nodecnt[p - 1], 1); \
                              p = sP[(v).z]; if (p) atomicAdd(&g_nodecnt[p - 1], 1); \
                              p = sP[(v).w]; if (p) atomicAdd(&g_nodecnt[p - 1], 1); }
    if (is64) {
        if ((E & 1) == 0) {
            const uint4* dv = (const uint4*)(w + 2L * E);
            int nv = E >> 1;
            int i = gid;
            for (; i + 3 * STR < nv; i += 4 * STR) {
                uint4 v0 = dv[i], v1 = dv[i + STR], v2 = dv[i + 2 * STR], v3 = dv[i + 3 * STR];
                unsigned a0 = sP[v0.x] | sP[v0.z];
                unsigned a1 = sP[v1.x] | sP[v1.z];
                unsigned a2 = sP[v2.x] | sP[v2.z];
                unsigned a3 = sP[v3.x] | sP[v3.z];
                if ((a0 | a1) | (a2 | a3)) { CNT2(v0); CNT2(v1); CNT2(v2); CNT2(v3); }
            }
            for (; i < nv; i += STR) {
                uint4 v = dv[i];
                if (sP[v.x] | sP[v.z]) { CNT2(v); }
            }
        } else {
            const long long* dst = ((const long long*)w) + E;
            for (long i = gid; i < E; i += STR) {
                unsigned p = sP[(unsigned)dst[i]];
                if (p) atomicAdd(&g_nodecnt[p - 1], 1);
            }
        }
    } else {
        if ((E & 3) == 0) {
            const uint4* dv = (const uint4*)(w + E);
            int nv = E >> 2;
            int i = gid;
            for (; i + 3 * STR < nv; i += 4 * STR) {
                uint4 v0 = dv[i], v1 = dv[i + STR], v2 = dv[i + 2 * STR], v3 = dv[i + 3 * STR];
                unsigned a0 = (sP[v0.x] | sP[v0.y]) | (sP[v0.z] | sP[v0.w]);
                unsigned a1 = (sP[v1.x] | sP[v1.y]) | (sP[v1.z] | sP[v1.w]);
                unsigned a2 = (sP[v2.x] | sP[v2.y]) | (sP[v2.z] | sP[v2.w]);
                unsigned a3 = (sP[v3.x] | sP[v3.y]) | (sP[v3.z] | sP[v3.w]);
                if ((a0 | a1) | (a2 | a3)) { CNT4(v0); CNT4(v1); CNT4(v2); CNT4(v3); }
            }
            for (; i < nv; i += STR) {
                uint4 v = dv[i];
                if ((sP[v.x] | sP[v.y]) | (sP[v.z] | sP[v.w])) { CNT4(v); }
            }
        } else {
            const int* dst = ((const int*)w) + E;
            for (long i = gid; i < E; i += STR) {
                unsigned p = sP[(unsigned)dst[i]];
                if (p) atomicAdd(&g_nodecnt[p - 1], 1);
            }
        }
    }
    gbar();  // -------- barrier 2 --------

    // ---------------- Encoder terms (block per term) + gh overlap ----------
    for (int i = bid; i < M; i += G) {
        int s = (i < cnt) ? g_srcs[i] : 0;
        float dg  = (float)g_nodecnt[sP[s] - 1] + 1.0f;   // +1 self loop
        float dg0 = (float)g_nodecnt[sP[0] - 1] + 1.0f;
        float wt = rsqrtf(dg) * rsqrtf(dg0);
        if (t < 64) sF[t] = nf[(long)s * 64 + t];
        __syncthreads();
        float f0 = sF[lane], f1 = sF[lane + 32];
        #pragma unroll
        for (int jj = 0; jj < 4; jj++) {
            int j = wid * 4 + jj;
            const float* wr = W_enc + j * 64;
            float a = wr[lane] * f0 + wr[lane + 32] * f1;
            #pragma unroll
            for (int o = 16; o; o >>= 1) a += __shfl_down_sync(0xffffffffu, a, o);
            if (lane == 0) g_ybuf[i][j] = wt * fmaxf(a + b_enc[j], 0.0f);
        }
        __syncthreads();
    }
    if (bid >= 96) {                      // gh = W_hh @ h + b_hh (indep of g0)
        int r = (bid - 96) * 32 + wid;
        if (r < 768) {
            const float* wr = W_hh + r * 256;
            float a = 0.0f;
            #pragma unroll
            for (int kk = 0; kk < 8; kk++) a += wr[kk * 32 + lane] * h[kk * 32 + lane];
            #pragma unroll
            for (int o = 16; o; o >>= 1) a += __shfl_down_sync(0xffffffffu, a, o);
            if (lane == 0) g_gh[r] = a + b_hh[r];
        }
    }
    gbar();  // -------- barrier 3 --------

    // ---------------- Block-0 tail: xsum, g0, gi, gates, reset -------------
    if (bid == 0) {
        float* sX  = (float*)sP;          // presence no longer needed: reuse smem
        float* sG0 = sX + 128;
        float* sGi = sG0 + 128;
        if (t < 128) {
            float xs = 0.0f;
            for (int i = 0; i < M; i++) xs += g_ybuf[i][t];
            sX[t] = xs;
        }
        __syncthreads();
        #pragma unroll
        for (int jj = 0; jj < 4; jj++) {
            int j = wid * 4 + jj;
            float a = 0.0f;
            #pragma unroll
            for (int kk = 0; kk < 4; kk++)
                a += W_gcn[j * 128 + kk * 32 + lane] * sX[kk * 32 + lane];
            #pragma unroll
            for (int o = 16; o; o >>= 1) a += __shfl_down_sync(0xffffffffu, a, o);
            if (lane == 0) sG0[j] = fmaxf(a + b_gcn[j], 0.0f);
        }
        __syncthreads();
        #pragma unroll
        for (int q = 0; q < 24; q++) {
            int r = q * 32 + wid;
            const float* wr = W_ih + r * 128;
            float a = 0.0f;
            #pragma unroll
            for (int kk = 0; kk < 4; kk++)
                a += wr[kk * 32 + lane] * sG0[kk * 32 + lane];
            #pragma unroll
            for (int o = 16; o; o >>= 1) a += __shfl_down_sync(0xffffffffu, a, o);
            if (lane == 0) sGi[r] = a + b_ih[r];
        }
        __syncthreads();
        if (t < 256) {
            float r_ = 1.0f / (1.0f + expf(-(sGi[t] + g_gh[t])));
            float z  = 1.0f / (1.0f + expf(-(sGi[256 + t] + g_gh[256 + t])));
            float nn = tanhf(sGi[512 + t] + r_ * g_gh[512 + t]);
            out[t] = (1.0f - z) * nn + z * h[t];
        }
        // reset device globals for the next (replayed) run
        for (int i = t; i < cnt + 2; i += B) g_nodecnt[i] = 0;
        if (t == 0) g_cnt = 0;
    }
}

// ---------------------------------------------------------------------------
extern "C" void kernel_launch(void* const* d_in, const int* in_sizes, int n_in,
                              void* d_out, int out_size) {
    const float* nf    = (const float*)d_in[0];
    // d_in[1] = edge_attr (unused by reference)
    const float* h     = (const float*)d_in[2];
    const float* W_enc = (const float*)d_in[3];
    const float* b_enc = (const float*)d_in[4];
    const float* W_gcn = (const float*)d_in[5];
    const float* b_gcn = (const float*)d_in[6];
    const float* W_ih  = (const float*)d_in[7];
    const float* W_hh  = (const float*)d_in[8];
    const float* b_ih  = (const float*)d_in[9];
    const float* b_hh  = (const float*)d_in[10];
    const unsigned* ei = (const unsigned*)d_in[11];
    int E = in_sizes[11] / 2;
    int N = in_sizes[0] / 64;
    float* out = (float*)d_out;

    int smem = (2 * N + 15) & ~15;
    if (smem < 8192) smem = 8192;                  // room for tail reuse arrays
    cudaFuncSetAttribute(k_fused, cudaFuncAttributeMaxDynamicSharedMemorySize, smem);

    k_fused<<<G, B, smem>>>(nf, h, W_enc, b_enc, W_gcn, b_gcn,
                            W_ih, W_hh, b_ih, b_hh, ei, E, N, out);
}

// round 8
// speedup vs baseline: 1.4848x; 1.4848x over previous
#include <cuda_runtime.h>

// ============================================================================
// STGCNEncoder — fused persistent kernel, v2.
// Only row 0 of the GCN output feeds the GRU.
//  Pass A: stream dst, unsigned-min trick to find dst==0 edges (~1.6 instr/edge)
//  Pass B: u16 presence table in smem -> exact degrees of the ~34-node set
//          (~2.6 instr/edge, rare global atomics on hits)
//  Then encoder GEMVs (block/term) + gh overlap, block-0 tail (g0, gi, gates).
//  3 grid barriers total. B=1024 for 8 warps/SMSP.
// ============================================================================

#define G   148
#define B   1024
#define STR (G * B)
#define CAP 2048

__device__ unsigned long long g_bar;       // monotonic grid-barrier counter
__device__ int   g_cnt;                    // # dst==0 edges (zeroed at end of run)
__device__ int   g_srcs[CAP];
__device__ int   g_nodecnt[CAP + 2];       // per-canonical-node indeg (zeroed at end)
__device__ float g_ybuf[CAP + 1][128];
__device__ float g_gh[768];

extern __shared__ unsigned short sP[];     // presence table, N u16 entries

__device__ __forceinline__ void gbar() {
    __threadfence();
    __syncthreads();
    if (threadIdx.x == 0) {
        unsigned long long t = atomicAdd(&g_bar, 1ULL);
        unsigned long long target = t - (t % G) + G;
        volatile unsigned long long* p = &g_bar;
        while (*p < target) __nanosleep(64);
    }
    __syncthreads();
    __threadfence();
}

__global__ void __launch_bounds__(B, 1) k_fused(
    const float* __restrict__ nf, const float* __restrict__ h,
    const float* __restrict__ W_enc, const float* __restrict__ b_enc,
    const float* __restrict__ W_gcn, const float* __restrict__ b_gcn,
    const float* __restrict__ W_ih, const float* __restrict__ W_hh,
    const float* __restrict__ b_ih, const float* __restrict__ b_hh,
    const unsigned* __restrict__ w, int E, int N, float* __restrict__ out)
{
    __shared__ int   sBad;
    __shared__ float sF[64];
    const int t = threadIdx.x, lane = t & 31, wid = t >> 5;
    const int bid = blockIdx.x;
    const int gid = bid * B + t;

    // zero presence table (16B stores)
    {
        int nw = (N + 7) >> 3;
        uint4* p4 = (uint4*)sP;
        uint4 z = make_uint4(0, 0, 0, 0);
        for (int i = t; i < nw; i += B) p4[i] = z;
    }
    if (t == 0) sBad = 0;
    __syncthreads();
    // dtype detect (per block, no grid barrier): int64 ids<2^31 => odd words 0
    {
        int bad = 0;
        for (int i = t; i < 2048 && i < E; i += B) bad |= (int)w[2 * i + 1];
        if (bad) atomicOr(&sBad, 1);
    }
    __syncthreads();
    const bool is64 = (sBad == 0);

    // ---------------- Pass A: collect srcs of dst==0 edges ----------------
    if (is64) {
        const long long* srcq = (const long long*)w;
        if ((E & 1) == 0) {
            const uint4* dv = (const uint4*)(w + 2L * E);  // dst as pairs of {lo,hi}
            int nv = E >> 1;
            int i = gid;
#define CHK64(v, j) { \
    if ((v).x == 0) { int p = atomicAdd(&g_cnt, 1); if (p < CAP) g_srcs[p] = (int)srcq[2L * (j)]; } \
    if ((v).z == 0) { int p = atomicAdd(&g_cnt, 1); if (p < CAP) g_srcs[p] = (int)srcq[2L * (j) + 1]; } }
            for (; i + 3 * STR < nv; i += 4 * STR) {
                uint4 v0 = dv[i], v1 = dv[i + STR], v2 = dv[i + 2 * STR], v3 = dv[i + 3 * STR];
                unsigned m = min(min(min(v0.x, v0.z), min(v1.x, v1.z)),
                                 min(min(v2.x, v2.z), min(v3.x, v3.z)));
                if (m == 0) { CHK64(v0, i); CHK64(v1, i + STR); CHK64(v2, i + 2 * STR); CHK64(v3, i + 3 * STR); }
            }
            for (; i < nv; i += STR) {
                uint4 v = dv[i];
                if (min(v.x, v.z) == 0) { CHK64(v, i); }
            }
        } else {
            const long long* dst = srcq + E;
            for (long i = gid; i < E; i += STR)
                if (dst[i] == 0) { int p = atomicAdd(&g_cnt, 1); if (p < CAP) g_srcs[p] = (int)srcq[i]; }
        }
    } else {
        const int* srci = (const int*)w;
        if ((E & 3) == 0) {
            const uint4* dv = (const uint4*)(w + E);
            int nv = E >> 2;
            int i = gid;
#define CHK32(v, j) { \
    if ((v).x == 0) { int p = atomicAdd(&g_cnt, 1); if (p < CAP) g_srcs[p] = srci[4L * (j)]; } \
    if ((v).y == 0) { int p = atomicAdd(&g_cnt, 1); if (p < CAP) g_srcs[p] = srci[4L * (j) + 1]; } \
    if ((v).z == 0) { int p = atomicAdd(&g_cnt, 1); if (p < CAP) g_srcs[p] = srci[4L * (j) + 2]; } \
    if ((v).w == 0) { int p = atomicAdd(&g_cnt, 1); if (p < CAP) g_srcs[p] = srci[4L * (j) + 3]; } }
            for (; i + 3 * STR < nv; i += 4 * STR) {
                uint4 v0 = dv[i], v1 = dv[i + STR], v2 = dv[i + 2 * STR], v3 = dv[i + 3 * STR];
                unsigned m = min(min(min(min(v0.x, v0.y), min(v0.z, v0.w)),
                                     min(min(v1.x, v1.y), min(v1.z, v1.w))),
                                 min(min(min(v2.x, v2.y), min(v2.z, v2.w)),
                                     min(min(v3.x, v3.y), min(v3.z, v3.w))));
                if (m == 0) { CHK32(v0, i); CHK32(v1, i + STR); CHK32(v2, i + 2 * STR); CHK32(v3, i + 3 * STR); }
            }
            for (; i < nv; i += STR) {
                uint4 v = dv[i];
                if (min(min(v.x, v.y), min(v.z, v.w)) == 0) { CHK32(v, i); }
            }
        } else {
            const int* dst = srci + E;
            for (long i = gid; i < E; i += STR)
                if (dst[i] == 0) { int p = atomicAdd(&g_cnt, 1); if (p < CAP) g_srcs[p] = srci[i]; }
        }
    }
    gbar();  // -------- barrier 1 --------

    int cnt = g_cnt; if (cnt > CAP) cnt = CAP;
    const int M = cnt + 1;                      // + node-0 self-loop term

    // build presence table (every block, deterministic last-write-wins order)
    if (t == 0) {
        for (int i = 0; i < cnt; i++) sP[g_srcs[i]] = (unsigned short)(i + 1);
        if (sP[0] == 0) sP[0] = (unsigned short)(cnt + 1);
    }
    __syncthreads();

    // ---------------- Pass B: count set-membership over dst ----------------
#define CNT2(v) { unsigned p; p = sP[(v).x]; if (p) atomicAdd(&g_nodecnt[p - 1], 1); \
                              p = sP[(v).z]; if (p) atomicAdd(&g_nodecnt[p - 1], 1); }
#define CNT4(v) { unsigned p; p = sP[(v).x]; if (p) atomicAdd(&g_nodecnt[p - 1], 1); \
                              p = sP[(v).y]; if (p) atomicAdd(&g_nodecnt[p - 1], 1); \
                              p = sP[(v).z]; if (p) atomicAdd(&g_nodecnt[p - 1], 1); \
                              p = sP[(v).w]; if (p) atomicAdd(&g_nodecnt[p - 1], 1); }
    if (is64) {
        if ((E & 1) == 0) {
            const uint4* dv = (const uint4*)(w + 2L * E);
            int nv = E >> 1;
            int i = gid;
            for (; i + 3 * STR < nv; i += 4 * STR) {
                uint4 v0 = dv[i], v1 = dv[i + STR], v2 = dv[i + 2 * STR], v3 = dv[i + 3 * STR];
                unsigned a0 = sP[v0.x] | sP[v0.z];
                unsigned a1 = sP[v1.x] | sP[v1.z];
                unsigned a2 = sP[v2.x] | sP[v2.z];
                unsigned a3 = sP[v3.x] | sP[v3.z];
                if ((a0 | a1) | (a2 | a3)) { CNT2(v0); CNT2(v1); CNT2(v2); CNT2(v3); }
            }
            for (; i < nv; i += STR) {
                uint4 v = dv[i];
                if (sP[v.x] | sP[v.z]) { CNT2(v); }
            }
        } else {
            const long long* dst = ((const long long*)w) + E;
            for (long i = gid; i < E; i += STR) {
                unsigned p = sP[(unsigned)dst[i]];
                if (p) atomicAdd(&g_nodecnt[p - 1], 1);
            }
        }
    } else {
        if ((E & 3) == 0) {
            const uint4* dv = (const uint4*)(w + E);
            int nv = E >> 2;
            int i = gid;
            for (; i + 3 * STR < nv; i += 4 * STR) {
                uint4 v0 = dv[i], v1 = dv[i + STR], v2 = dv[i + 2 * STR], v3 = dv[i + 3 * STR];
                unsigned a0 = (sP[v0.x] | sP[v0.y]) | (sP[v0.z] | sP[v0.w]);
                unsigned a1 = (sP[v1.x] | sP[v1.y]) | (sP[v1.z] | sP[v1.w]);
                unsigned a2 = (sP[v2.x] | sP[v2.y]) | (sP[v2.z] | sP[v2.w]);
                unsigned a3 = (sP[v3.x] | sP[v3.y]) | (sP[v3.z] | sP[v3.w]);
                if ((a0 | a1) | (a2 | a3)) { CNT4(v0); CNT4(v1); CNT4(v2); CNT4(v3); }
            }
            for (; i < nv; i += STR) {
                uint4 v = dv[i];
                if ((sP[v.x] | sP[v.y]) | (sP[v.z] | sP[v.w])) { CNT4(v); }
            }
        } else {
            const int* dst = ((const int*)w) + E;
            for (long i = gid; i < E; i += STR) {
                unsigned p = sP[(unsigned)dst[i]];
                if (p) atomicAdd(&g_nodecnt[p - 1], 1);
            }
        }
    }
    gbar();  // -------- barrier 2 --------

    // ---------------- Encoder terms (block per term) + gh overlap ----------
    for (int i = bid; i < M; i += G) {
        int s = (i < cnt) ? g_srcs[i] : 0;
        float dg  = (float)g_nodecnt[sP[s] - 1] + 1.0f;   // +1 self loop
        float dg0 = (float)g_nodecnt[sP[0] - 1] + 1.0f;
        float wt = rsqrtf(dg) * rsqrtf(dg0);
        if (t < 64) sF[t] = nf[(long)s * 64 + t];
        __syncthreads();
        float f0 = sF[lane], f1 = sF[lane + 32];
        #pragma unroll
        for (int jj = 0; jj < 4; jj++) {
            int j = wid * 4 + jj;
            const float* wr = W_enc + j * 64;
            float a = wr[lane] * f0 + wr[lane + 32] * f1;
            #pragma unroll
            for (int o = 16; o; o >>= 1) a += __shfl_down_sync(0xffffffffu, a, o);
            if (lane == 0) g_ybuf[i][j] = wt * fmaxf(a + b_enc[j], 0.0f);
        }
        __syncthreads();
    }
    if (bid >= 96) {                      // gh = W_hh @ h + b_hh (indep of g0)
        int r = (bid - 96) * 32 + wid;
        if (r < 768) {
            const float* wr = W_hh + r * 256;
            float a = 0.0f;
            #pragma unroll
            for (int kk = 0; kk < 8; kk++) a += wr[kk * 32 + lane] * h[kk * 32 + lane];
            #pragma unroll
            for (int o = 16; o; o >>= 1) a += __shfl_down_sync(0xffffffffu, a, o);
            if (lane == 0) g_gh[r] = a + b_hh[r];
        }
    }
    gbar();  // -------- barrier 3 --------

    // ---------------- Block-0 tail: xsum, g0, gi, gates, reset -------------
    if (bid == 0) {
        float* sX  = (float*)sP;          // presence no longer needed: reuse smem
        float* sG0 = sX + 128;
        float* sGi = sG0 + 128;
        if (t < 128) {
            float xs = 0.0f;
            for (int i = 0; i < M; i++) xs += g_ybuf[i][t];
            sX[t] = xs;
        }
        __syncthreads();
        #pragma unroll
        for (int jj = 0; jj < 4; jj++) {
            int j = wid * 4 + jj;
            float a = 0.0f;
            #pragma unroll
            for (int kk = 0; kk < 4; kk++)
                a += W_gcn[j * 128 + kk * 32 + lane] * sX[kk * 32 + lane];
            #pragma unroll
            for (int o = 16; o; o >>= 1) a += __shfl_down_sync(0xffffffffu, a, o);
            if (lane == 0) sG0[j] = fmaxf(a + b_gcn[j], 0.0f);
        }
        __syncthreads();
        #pragma unroll
        for (int q = 0; q < 24; q++) {
            int r = q * 32 + wid;
            const float* wr = W_ih + r * 128;
            float a = 0.0f;
            #pragma unroll
            for (int kk = 0; kk < 4; kk++)
                a += wr[kk * 32 + lane] * sG0[kk * 32 + lane];
            #pragma unroll
            for (int o = 16; o; o >>= 1) a += __shfl_down_sync(0xffffffffu, a, o);
            if (lane == 0) sGi[r] = a + b_ih[r];
        }
        __syncthreads();
        if (t < 256) {
            float r_ = 1.0f / (1.0f + expf(-(sGi[t] + g_gh[t])));
            float z  = 1.0f / (1.0f + expf(-(sGi[256 + t] + g_gh[256 + t])));
            float nn = tanhf(sGi[512 + t] + r_ * g_gh[512 + t]);
            out[t] = (1.0f - z) * nn + z * h[t];
        }
        // reset device globals for the next (replayed) run
        for (int i = t; i < cnt + 2; i += B) g_nodecnt[i] = 0;
        if (t == 0) g_cnt = 0;
    }
}

// ---------------------------------------------------------------------------
extern "C" void kernel_launch(void* const* d_in, const int* in_sizes, int n_in,
                              void* d_out, int out_size) {
    const float* nf    = (const float*)d_in[0];
    // d_in[1] = edge_attr (unused by reference)
    const float* h     = (const float*)d_in[2];
    const float* W_enc = (const float*)d_in[3];
    const float* b_enc = (const float*)d_in[4];
    const float* W_gcn = (const float*)d_in[5];
    const float* b_gcn = (const float*)d_in[6];
    const float* W_ih  = (const float*)d_in[7];
    const float* W_hh  = (const float*)d_in[8];
    const float* b_ih  = (const float*)d_in[9];
    const float* b_hh  = (const float*)d_in[10];
    const unsigned* ei = (const unsigned*)d_in[11];
    int E = in_sizes[11] / 2;
    int N = in_sizes[0] / 64;
    float* out = (float*)d_out;

    int smem = (2 * N + 15) & ~15;
    if (smem < 8192) smem = 8192;                  // room for tail reuse arrays
    cudaFuncSetAttribute(k_fused, cudaFuncAttributeMaxDynamicSharedMemorySize, smem);

    k_fused<<<G, B, smem>>>(nf, h, W_enc, b_enc, W_gcn, b_gcn,
                            W_ih, W_hh, b_ih, b_hh, ei, E, N, out);
}

// round 9
// speedup vs baseline: 1.4943x; 1.0064x over previous
#include <cuda_runtime.h>

// ============================================================================
// STGCNEncoder — fused persistent kernel, v2.
// Only row 0 of the GCN output feeds the GRU.
//  Pass A: stream dst, unsigned-min trick to find dst==0 edges (~1.6 instr/edge)
//  Pass B: u16 presence table in smem -> exact degrees of the ~34-node set
//          (~2.6 instr/edge, rare global atomics on hits)
//  Then encoder GEMVs (block/term) + gh overlap, block-0 tail (g0, gi, gates).
//  3 grid barriers total. B=1024 for 8 warps/SMSP.
// ============================================================================

#define G   148
#define B   1024
#define STR (G * B)
#define CAP 2048

__device__ unsigned long long g_bar;       // monotonic grid-barrier counter
__device__ int   g_cnt;                    // # dst==0 edges (zeroed at end of run)
__device__ int   g_srcs[CAP];
__device__ int   g_nodecnt[CAP + 2];       // per-canonical-node indeg (zeroed at end)
__device__ float g_ybuf[CAP + 1][128];
__device__ float g_gh[768];

extern __shared__ unsigned short sP[];     // presence table, N u16 entries

__device__ __forceinline__ void gbar() {
    __threadfence();
    __syncthreads();
    if (threadIdx.x == 0) {
        unsigned long long t = atomicAdd(&g_bar, 1ULL);
        unsigned long long target = t - (t % G) + G;
        volatile unsigned long long* p = &g_bar;
        while (*p < target) __nanosleep(64);
    }
    __syncthreads();
    __threadfence();
}

__global__ void __launch_bounds__(B, 1) k_fused(
    const float* __restrict__ nf, const float* __restrict__ h,
    const float* __restrict__ W_enc, const float* __restrict__ b_enc,
    const float* __restrict__ W_gcn, const float* __restrict__ b_gcn,
    const float* __restrict__ W_ih, const float* __restrict__ W_hh,
    const float* __restrict__ b_ih, const float* __restrict__ b_hh,
    const unsigned* __restrict__ w, int E, int N, float* __restrict__ out)
{
    __shared__ int   sBad;
    __shared__ float sF[64];
    const int t = threadIdx.x, lane = t & 31, wid = t >> 5;
    const int bid = blockIdx.x;
    const int gid = bid * B + t;

    // zero presence table (16B stores)
    {
        int nw = (N + 7) >> 3;
        uint4* p4 = (uint4*)sP;
        uint4 z = make_uint4(0, 0, 0, 0);
        for (int i = t; i < nw; i += B) p4[i] = z;
    }
    if (t == 0) sBad = 0;
    __syncthreads();
    // dtype detect (per block, no grid barrier): int64 ids<2^31 => odd words 0
    {
        int bad = 0;
        for (int i = t; i < 2048 && i < E; i += B) bad |= (int)w[2 * i + 1];
        if (bad) atomicOr(&sBad, 1);
    }
    __syncthreads();
    const bool is64 = (sBad == 0);

    // ---------------- Pass A: collect srcs of dst==0 edges ----------------
    if (is64) {
        const long long* srcq = (const long long*)w;
        if ((E & 1) == 0) {
            const uint4* dv = (const uint4*)(w + 2L * E);  // dst as pairs of {lo,hi}
            int nv = E >> 1;
            int i = gid;
#define CHK64(v, j) { \
    if ((v).x == 0) { int p = atomicAdd(&g_cnt, 1); if (p < CAP) g_srcs[p] = (int)srcq[2L * (j)]; } \
    if ((v).z == 0) { int p = atomicAdd(&g_cnt, 1); if (p < CAP) g_srcs[p] = (int)srcq[2L * (j) + 1]; } }
            for (; i + 3 * STR < nv; i += 4 * STR) {
                uint4 v0 = dv[i], v1 = dv[i + STR], v2 = dv[i + 2 * STR], v3 = dv[i + 3 * STR];
                unsigned m = min(min(min(v0.x, v0.z), min(v1.x, v1.z)),
                                 min(min(v2.x, v2.z), min(v3.x, v3.z)));
                if (m == 0) { CHK64(v0, i); CHK64(v1, i + STR); CHK64(v2, i + 2 * STR); CHK64(v3, i + 3 * STR); }
            }
            for (; i < nv; i += STR) {
                uint4 v = dv[i];
                if (min(v.x, v.z) == 0) { CHK64(v, i); }
            }
        } else {
            const long long* dst = srcq + E;
            for (long i = gid; i < E; i += STR)
                if (dst[i] == 0) { int p = atomicAdd(&g_cnt, 1); if (p < CAP) g_srcs[p] = (int)srcq[i]; }
        }
    } else {
        const int* srci = (const int*)w;
        if ((E & 3) == 0) {
            const uint4* dv = (const uint4*)(w + E);
            int nv = E >> 2;
            int i = gid;
#define CHK32(v, j) { \
    if ((v).x == 0) { int p = atomicAdd(&g_cnt, 1); if (p < CAP) g_srcs[p] = srci[4L * (j)]; } \
    if ((v).y == 0) { int p = atomicAdd(&g_cnt, 1); if (p < CAP) g_srcs[p] = srci[4L * (j) + 1]; } \
    if ((v).z == 0) { int p = atomicAdd(&g_cnt, 1); if (p < CAP) g_srcs[p] = srci[4L * (j) + 2]; } \
    if ((v).w == 0) { int p = atomicAdd(&g_cnt, 1); if (p < CAP) g_srcs[p] = srci[4L * (j) + 3]; } }
            for (; i + 3 * STR < nv; i += 4 * STR) {
                uint4 v0 = dv[i], v1 = dv[i + STR], v2 = dv[i + 2 * STR], v3 = dv[i + 3 * STR];
                unsigned m = min(min(min(min(v0.x, v0.y), min(v0.z, v0.w)),
                                     min(min(v1.x, v1.y), min(v1.z, v1.w))),
                                 min(min(min(v2.x, v2.y), min(v2.z, v2.w)),
                                     min(min(v3.x, v3.y), min(v3.z, v3.w))));
                if (m == 0) { CHK32(v0, i); CHK32(v1, i + STR); CHK32(v2, i + 2 * STR); CHK32(v3, i + 3 * STR); }
            }
            for (; i < nv; i += STR) {
                uint4 v = dv[i];
                if (min(min(v.x, v.y), min(v.z, v.w)) == 0) { CHK32(v, i); }
            }
        } else {
            const int* dst = srci + E;
            for (long i = gid; i < E; i += STR)
                if (dst[i] == 0) { int p = atomicAdd(&g_cnt, 1); if (p < CAP) g_srcs[p] = srci[i]; }
        }
    }
    gbar();  // -------- barrier 1 --------

    int cnt = g_cnt; if (cnt > CAP) cnt = CAP;
    const int M = cnt + 1;                      // + node-0 self-loop term

    // build presence table (every block, deterministic last-write-wins order)
    if (t == 0) {
        for (int i = 0; i < cnt; i++) sP[g_srcs[i]] = (unsigned short)(i + 1);
        if (sP[0] == 0) sP[0] = (unsigned short)(cnt + 1);
    }
    __syncthreads();

    // ---------------- Pass B: count set-membership over dst ----------------
#define CNT2(v) { unsigned p; p = sP[(v).x]; if (p) atomicAdd(&g_nodecnt[p - 1], 1); \
                              p = sP[(v).z]; if (p) atomicAdd(&g_nodecnt[p - 1], 1); }
#define CNT4(v) { unsigned p; p = sP[(v).x]; if (p) atomicAdd(&g_nodecnt[p - 1], 1); \
                              p = sP[(v).y]; if (p) atomicAdd(&g_nodecnt[p - 1], 1); \
                              p = sP[(v).z]; if (p) atomicAdd(&g_nodecnt[p - 1], 1); \
                              p = sP[(v).w]; if (p) atomicAdd(&g_nodecnt[p - 1], 1); }
    if (is64) {
        if ((E & 1) == 0) {
            const uint4* dv = (const uint4*)(w + 2L * E);
            int nv = E >> 1;
            int i = gid;
            for (; i + 3 * STR < nv; i += 4 * STR) {
                uint4 v0 = dv[i], v1 = dv[i + STR], v2 = dv[i + 2 * STR], v3 = dv[i + 3 * STR];
                unsigned a0 = sP[v0.x] | sP[v0.z];
                unsigned a1 = sP[v1.x] | sP[v1.z];
                unsigned a2 = sP[v2.x] | sP[v2.z];
                unsigned a3 = sP[v3.x] | sP[v3.z];
                if ((a0 | a1) | (a2 | a3)) { CNT2(v0); CNT2(v1); CNT2(v2); CNT2(v3); }
            }
            for (; i < nv; i += STR) {
                uint4 v = dv[i];
                if (sP[v.x] | sP[v.z]) { CNT2(v); }
            }
        } else {
            const long long* dst = ((const long long*)w) + E;
            for (long i = gid; i < E; i += STR) {
                unsigned p = sP[(unsigned)dst[i]];
                if (p) atomicAdd(&g_nodecnt[p - 1], 1);
            }
        }
    } else {
        if ((E & 3) == 0) {
            const uint4* dv = (const uint4*)(w + E);
            int nv = E >> 2;
            int i = gid;
            for (; i + 3 * STR < nv; i += 4 * STR) {
                uint4 v0 = dv[i], v1 = dv[i + STR], v2 = dv[i + 2 * STR], v3 = dv[i + 3 * STR];
                unsigned a0 = (sP[v0.x] | sP[v0.y]) | (sP[v0.z] | sP[v0.w]);
                unsigned a1 = (sP[v1.x] | sP[v1.y]) | (sP[v1.z] | sP[v1.w]);
                unsigned a2 = (sP[v2.x] | sP[v2.y]) | (sP[v2.z] | sP[v2.w]);
                unsigned a3 = (sP[v3.x] | sP[v3.y]) | (sP[v3.z] | sP[v3.w]);
                if ((a0 | a1) | (a2 | a3)) { CNT4(v0); CNT4(v1); CNT4(v2); CNT4(v3); }
            }
            for (; i < nv; i += STR) {
                uint4 v = dv[i];
                if ((sP[v.x] | sP[v.y]) | (sP[v.z] | sP[v.w])) { CNT4(v); }
            }
        } else {
            const int* dst = ((const int*)w) + E;
            for (long i = gid; i < E; i += STR) {
                unsigned p = sP[(unsigned)dst[i]];
                if (p) atomicAdd(&g_nodecnt[p - 1], 1);
            }
        }
    }
    gbar();  // -------- barrier 2 --------

    // ---------------- Encoder terms (block per term) + gh overlap ----------
    for (int i = bid; i < M; i += G) {
        int s = (i < cnt) ? g_srcs[i] : 0;
        float dg  = (float)g_nodecnt[sP[s] - 1] + 1.0f;   // +1 self loop
        float dg0 = (float)g_nodecnt[sP[0] - 1] + 1.0f;
        float wt = rsqrtf(dg) * rsqrtf(dg0);
        if (t < 64) sF[t] = nf[(long)s * 64 + t];
        __syncthreads();
        float f0 = sF[lane], f1 = sF[lane + 32];
        #pragma unroll
        for (int jj = 0; jj < 4; jj++) {
            int j = wid * 4 + jj;
            const float* wr = W_enc + j * 64;
            float a = wr[lane] * f0 + wr[lane + 32] * f1;
            #pragma unroll
            for (int o = 16; o; o >>= 1) a += __shfl_down_sync(0xffffffffu, a, o);
            if (lane == 0) g_ybuf[i][j] = wt * fmaxf(a + b_enc[j], 0.0f);
        }
        __syncthreads();
    }
    if (bid >= 96) {                      // gh = W_hh @ h + b_hh (indep of g0)
        int r = (bid - 96) * 32 + wid;
        if (r < 768) {
            const float* wr = W_hh + r * 256;
            float a = 0.0f;
            #pragma unroll
            for (int kk = 0; kk < 8; kk++) a += wr[kk * 32 + lane] * h[kk * 32 + lane];
            #pragma unroll
            for (int o = 16; o; o >>= 1) a += __shfl_down_sync(0xffffffffu, a, o);
            if (lane == 0) g_gh[r] = a + b_hh[r];
        }
    }
    gbar();  // -------- barrier 3 --------

    // ---------------- Block-0 tail: xsum, g0, gi, gates, reset -------------
    if (bid == 0) {
        float* sX  = (float*)sP;          // presence no longer needed: reuse smem
        float* sG0 = sX + 128;
        float* sGi = sG0 + 128;
        if (t < 128) {
            float xs = 0.0f;
            for (int i = 0; i < M; i++) xs += g_ybuf[i][t];
            sX[t] = xs;
        }
        __syncthreads();
        #pragma unroll
        for (int jj = 0; jj < 4; jj++) {
            int j = wid * 4 + jj;
            float a = 0.0f;
            #pragma unroll
            for (int kk = 0; kk < 4; kk++)
                a += W_gcn[j * 128 + kk * 32 + lane] * sX[kk * 32 + lane];
            #pragma unroll
            for (int o = 16; o; o >>= 1) a += __shfl_down_sync(0xffffffffu, a, o);
            if (lane == 0) sG0[j] = fmaxf(a + b_gcn[j], 0.0f);
        }
        __syncthreads();
        #pragma unroll
        for (int q = 0; q < 24; q++) {
            int r = q * 32 + wid;
            const float* wr = W_ih + r * 128;
            float a = 0.0f;
            #pragma unroll
            for (int kk = 0; kk < 4; kk++)
                a += wr[kk * 32 + lane] * sG0[kk * 32 + lane];
            #pragma unroll
            for (int o = 16; o; o >>= 1) a += __shfl_down_sync(0xffffffffu, a, o);
            if (lane == 0) sGi[r] = a + b_ih[r];
        }
        __syncthreads();
        if (t < 256) {
            float r_ = 1.0f / (1.0f + expf(-(sGi[t] + g_gh[t])));
            float z  = 1.0f / (1.0f + expf(-(sGi[256 + t] + g_gh[256 + t])));
            float nn = tanhf(sGi[512 + t] + r_ * g_gh[512 + t]);
            out[t] = (1.0f - z) * nn + z * h[t];
        }
        // reset device globals for the next (replayed) run
        for (int i = t; i < cnt + 2; i += B) g_nodecnt[i] = 0;
        if (t == 0) g_cnt = 0;
    }
}

// ---------------------------------------------------------------------------
extern "C" void kernel_launch(void* const* d_in, const int* in_sizes, int n_in,
                              void* d_out, int out_size) {
    const float* nf    = (const float*)d_in[0];
    // d_in[1] = edge_attr (unused by reference)
    const float* h     = (const float*)d_in[2];
    const float* W_enc = (const float*)d_in[3];
    const float* b_enc = (const float*)d_in[4];
    const float* W_gcn = (const float*)d_in[5];
    const float* b_gcn = (const float*)d_in[6];
    const float* W_ih  = (const float*)d_in[7];
    const float* W_hh  = (const float*)d_in[8];
    const float* b_ih  = (const float*)d_in[9];
    const float* b_hh  = (const float*)d_in[10];
    const unsigned* ei = (const unsigned*)d_in[11];
    int E = in_sizes[11] / 2;
    int N = in_sizes[0] / 64;
    float* out = (float*)d_out;

    int smem = (2 * N + 15) & ~15;
    if (smem < 8192) smem = 8192;                  // room for tail reuse arrays
    cudaFuncSetAttribute(k_fused, cudaFuncAttributeMaxDynamicSharedMemorySize, smem);

    k_fused<<<G, B, smem>>>(nf, h, W_enc, b_enc, W_gcn, b_gcn,
                            W_ih, W_hh, b_ih, b_hh, ei, E, N, out);
}

// round 10
// speedup vs baseline: 1.5000x; 1.0038x over previous
#include <cuda_runtime.h>

// ============================================================================
// STGCNEncoder — fused persistent kernel, v3.
// Only row 0 of the GCN output feeds the GRU.
//  Pass A: stream dst, unsigned-min trick finds dst==0 edges. 8x uint4 MLP.
//  Pass B: u16 presence table in smem -> exact degrees of the ~34-node set.
//          8x uint4 LDG batch, per-vector presence test, rare global atomics.
//  Then encoder GEMVs (block/term) + gh overlap, block-0 tail (g0, gi, gates).
//  3 grid barriers. B=1024 (32 warps/SM), 1 block/SM (200KB smem).
// ============================================================================

#define G   148
#define B   1024
#define STR (G * B)
#define CAP 2048
#define U   8

__device__ unsigned long long g_bar;       // monotonic grid-barrier counter
__device__ int   g_cnt;                    // # dst==0 edges (zeroed at end of run)
__device__ int   g_srcs[CAP];
__device__ int   g_nodecnt[CAP + 2];       // per-canonical-node indeg (zeroed at end)
__device__ float g_ybuf[CAP + 1][128];
__device__ float g_gh[768];

extern __shared__ unsigned short sP[];     // presence table, N u16 entries

__device__ __forceinline__ void gbar() {
    __threadfence();
    __syncthreads();
    if (threadIdx.x == 0) {
        unsigned long long t = atomicAdd(&g_bar, 1ULL);
        unsigned long long target = t - (t % G) + G;
        volatile unsigned long long* p = &g_bar;
        while (*p < target) __nanosleep(32);
    }
    __syncthreads();
    __threadfence();
}

__global__ void __launch_bounds__(B, 1) k_fused(
    const float* __restrict__ nf, const float* __restrict__ h,
    const float* __restrict__ W_enc, const float* __restrict__ b_enc,
    const float* __restrict__ W_gcn, const float* __restrict__ b_gcn,
    const float* __restrict__ W_ih, const float* __restrict__ W_hh,
    const float* __restrict__ b_ih, const float* __restrict__ b_hh,
    const unsigned* __restrict__ w, int E, int N, float* __restrict__ out)
{
    __shared__ int   sBad;
    __shared__ float sF[64];
    const int t = threadIdx.x, lane = t & 31, wid = t >> 5;
    const int bid = blockIdx.x;
    const int gid = bid * B + t;

    // zero presence table (16B stores)
    {
        int nw = (N + 7) >> 3;
        uint4* p4 = (uint4*)sP;
        uint4 z = make_uint4(0, 0, 0, 0);
        for (int i = t; i < nw; i += B) p4[i] = z;
    }
    if (t == 0) sBad = 0;
    __syncthreads();
    // dtype detect (per block): int64 ids < 2^31 => every odd word is 0
    {
        int bad = 0;
        for (int i = t; i < 2048 && i < E; i += B) bad |= (int)w[2 * i + 1];
        if (bad) atomicOr(&sBad, 1);
    }
    __syncthreads();
    const bool is64 = (sBad == 0);

    // ---------------- Pass A: collect srcs of dst==0 edges ----------------
    if (is64) {
        const long long* srcq = (const long long*)w;
        if ((E & 1) == 0) {
            const uint4* dv = (const uint4*)(w + 2L * E);  // {lo,hi,lo,hi}
            int nv = E >> 1;
            int i = gid;
            for (; i + (U - 1) * STR < nv; i += U * STR) {
                uint4 v[U];
                #pragma unroll
                for (int j = 0; j < U; j++) v[j] = dv[i + j * STR];
                unsigned m = 0xffffffffu;
                #pragma unroll
                for (int j = 0; j < U; j++) m = min(m, min(v[j].x, v[j].z));
                if (m == 0) {
                    #pragma unroll
                    for (int j = 0; j < U; j++) {
                        long e = 2L * (i + j * STR);
                        if (v[j].x == 0) { int p = atomicAdd(&g_cnt, 1); if (p < CAP) g_srcs[p] = (int)srcq[e]; }
                        if (v[j].z == 0) { int p = atomicAdd(&g_cnt, 1); if (p < CAP) g_srcs[p] = (int)srcq[e + 1]; }
                    }
                }
            }
            for (; i < nv; i += STR) {
                uint4 v = dv[i];
                if (min(v.x, v.z) == 0) {
                    long e = 2L * i;
                    if (v.x == 0) { int p = atomicAdd(&g_cnt, 1); if (p < CAP) g_srcs[p] = (int)srcq[e]; }
                    if (v.z == 0) { int p = atomicAdd(&g_cnt, 1); if (p < CAP) g_srcs[p] = (int)srcq[e + 1]; }
                }
            }
        } else {
            const long long* dst = srcq + E;
            for (long i = gid; i < E; i += STR)
                if (dst[i] == 0) { int p = atomicAdd(&g_cnt, 1); if (p < CAP) g_srcs[p] = (int)srcq[i]; }
        }
    } else {
        const int* srci = (const int*)w;
        if ((E & 3) == 0) {
            const uint4* dv = (const uint4*)(w + E);
            int nv = E >> 2;
            int i = gid;
            for (; i + (U - 1) * STR < nv; i += U * STR) {
                uint4 v[U];
                #pragma unroll
                for (int j = 0; j < U; j++) v[j] = dv[i + j * STR];
                unsigned m = 0xffffffffu;
                #pragma unroll
                for (int j = 0; j < U; j++)
                    m = min(m, min(min(v[j].x, v[j].y), min(v[j].z, v[j].w)));
                if (m == 0) {
                    #pragma unroll
                    for (int j = 0; j < U; j++) {
                        long e = 4L * (i + j * STR);
                        if (v[j].x == 0) { int p = atomicAdd(&g_cnt, 1); if (p < CAP) g_srcs[p] = srci[e]; }
                        if (v[j].y == 0) { int p = atomicAdd(&g_cnt, 1); if (p < CAP) g_srcs[p] = srci[e + 1]; }
                        if (v[j].z == 0) { int p = atomicAdd(&g_cnt, 1); if (p < CAP) g_srcs[p] = srci[e + 2]; }
                        if (v[j].w == 0) { int p = atomicAdd(&g_cnt, 1); if (p < CAP) g_srcs[p] = srci[e + 3]; }
                    }
                }
            }
            for (; i < nv; i += STR) {
                uint4 v = dv[i];
                if (min(min(v.x, v.y), min(v.z, v.w)) == 0) {
                    long e = 4L * i;
                    if (v.x == 0) { int p = atomicAdd(&g_cnt, 1); if (p < CAP) g_srcs[p] = srci[e]; }
                    if (v.y == 0) { int p = atomicAdd(&g_cnt, 1); if (p < CAP) g_srcs[p] = srci[e + 1]; }
                    if (v.z == 0) { int p = atomicAdd(&g_cnt, 1); if (p < CAP) g_srcs[p] = srci[e + 2]; }
                    if (v.w == 0) { int p = atomicAdd(&g_cnt, 1); if (p < CAP) g_srcs[p] = srci[e + 3]; }
                }
            }
        } else {
            const int* dst = srci + E;
            for (long i = gid; i < E; i += STR)
                if (dst[i] == 0) { int p = atomicAdd(&g_cnt, 1); if (p < CAP) g_srcs[p] = srci[i]; }
        }
    }
    gbar();  // -------- barrier 1 --------

    int cnt = g_cnt; if (cnt > CAP) cnt = CAP;
    const int M = cnt + 1;                      // + node-0 self-loop term

    // build presence table (every block, deterministic order)
    if (t == 0) {
        for (int i = 0; i < cnt; i++) sP[g_srcs[i]] = (unsigned short)(i + 1);
        if (sP[0] == 0) sP[0] = (unsigned short)(cnt + 1);
    }
    __syncthreads();

    // ---------------- Pass B: count set-membership over dst ----------------
    if (is64) {
        if ((E & 1) == 0) {
            const uint4* dv = (const uint4*)(w + 2L * E);
            int nv = E >> 1;
            int i = gid;
            for (; i + (U - 1) * STR < nv; i += U * STR) {
                uint4 v[U];
                #pragma unroll
                for (int j = 0; j < U; j++) v[j] = dv[i + j * STR];
                #pragma unroll
                for (int j = 0; j < U; j++) {
                    unsigned p0 = sP[v[j].x], p1 = sP[v[j].z];
                    if (p0 | p1) {
                        if (p0) atomicAdd(&g_nodecnt[p0 - 1], 1);
                        if (p1) atomicAdd(&g_nodecnt[p1 - 1], 1);
                    }
                }
            }
            for (; i < nv; i += STR) {
                uint4 v = dv[i];
                unsigned p0 = sP[v.x], p1 = sP[v.z];
                if (p0) atomicAdd(&g_nodecnt[p0 - 1], 1);
                if (p1) atomicAdd(&g_nodecnt[p1 - 1], 1);
            }
        } else {
            const long long* dst = ((const long long*)w) + E;
            for (long i = gid; i < E; i += STR) {
                unsigned p = sP[(unsigned)dst[i]];
                if (p) atomicAdd(&g_nodecnt[p - 1], 1);
            }
        }
    } else {
        if ((E & 3) == 0) {
            const uint4* dv = (const uint4*)(w + E);
            int nv = E >> 2;
            int i = gid;
            for (; i + (U - 1) * STR < nv; i += U * STR) {
                uint4 v[U];
                #pragma unroll
                for (int j = 0; j < U; j++) v[j] = dv[i + j * STR];
                #pragma unroll
                for (int j = 0; j < U; j++) {
                    unsigned p0 = sP[v[j].x], p1 = sP[v[j].y];
                    unsigned p2 = sP[v[j].z], p3 = sP[v[j].w];
                    if ((p0 | p1) | (p2 | p3)) {
                        if (p0) atomicAdd(&g_nodecnt[p0 - 1], 1);
                        if (p1) atomicAdd(&g_nodecnt[p1 - 1], 1);
                        if (p2) atomicAdd(&g_nodecnt[p2 - 1], 1);
                        if (p3) atomicAdd(&g_nodecnt[p3 - 1], 1);
                    }
                }
            }
            for (; i < nv; i += STR) {
                uint4 v = dv[i];
                unsigned p0 = sP[v.x], p1 = sP[v.y];
                unsigned p2 = sP[v.z], p3 = sP[v.w];
                if (p0) atomicAdd(&g_nodecnt[p0 - 1], 1);
                if (p1) atomicAdd(&g_nodecnt[p1 - 1], 1);
                if (p2) atomicAdd(&g_nodecnt[p2 - 1], 1);
                if (p3) atomicAdd(&g_nodecnt[p3 - 1], 1);
            }
        } else {
            const int* dst = ((const int*)w) + E;
            for (long i = gid; i < E; i += STR) {
                unsigned p = sP[(unsigned)dst[i]];
                if (p) atomicAdd(&g_nodecnt[p - 1], 1);
            }
        }
    }
    gbar();  // -------- barrier 2 --------

    // ---------------- Encoder terms (block per term) + gh overlap ----------
    for (int i = bid; i < M; i += G) {
        int s = (i < cnt) ? g_srcs[i] : 0;
        float dg  = (float)g_nodecnt[sP[s] - 1] + 1.0f;   // +1 self loop
        float dg0 = (float)g_nodecnt[sP[0] - 1] + 1.0f;
        float wt = rsqrtf(dg) * rsqrtf(dg0);
        if (t < 64) sF[t] = nf[(long)s * 64 + t];
        __syncthreads();
        float f0 = sF[lane], f1 = sF[lane + 32];
        #pragma unroll
        for (int jj = 0; jj < 4; jj++) {
            int j = wid * 4 + jj;
            const float* wr = W_enc + j * 64;
            float a = wr[lane] * f0 + wr[lane + 32] * f1;
            #pragma unroll
            for (int o = 16; o; o >>= 1) a += __shfl_down_sync(0xffffffffu, a, o);
            if (lane == 0) g_ybuf[i][j] = wt * fmaxf(a + b_enc[j], 0.0f);
        }
        __syncthreads();
    }
    if (bid >= 96) {                      // gh = W_hh @ h + b_hh (indep of g0)
        int r = (bid - 96) * 32 + wid;
        if (r < 768) {
            const float* wr = W_hh + r * 256;
            float a = 0.0f;
            #pragma unroll
            for (int kk = 0; kk < 8; kk++) a += wr[kk * 32 + lane] * h[kk * 32 + lane];
            #pragma unroll
            for (int o = 16; o; o >>= 1) a += __shfl_down_sync(0xffffffffu, a, o);
            if (lane == 0) g_gh[r] = a + b_hh[r];
        }
    }
    gbar();  // -------- barrier 3 --------

    // ---------------- Block-0 tail: xsum, g0, gi, gates, reset -------------
    if (bid == 0) {
        float* sX  = (float*)sP;          // presence no longer needed: reuse smem
        float* sG0 = sX + 128;
        float* sGi = sG0 + 128;
        if (t < 128) {
            float xs = 0.0f;
            for (int i = 0; i < M; i++) xs += g_ybuf[i][t];
            sX[t] = xs;
        }
        __syncthreads();
        #pragma unroll
        for (int jj = 0; jj < 4; jj++) {
            int j = wid * 4 + jj;
            float a = 0.0f;
            #pragma unroll
            for (int kk = 0; kk < 4; kk++)
                a += W_gcn[j * 128 + kk * 32 + lane] * sX[kk * 32 + lane];
            #pragma unroll
            for (int o = 16; o; o >>= 1) a += __shfl_down_sync(0xffffffffu, a, o);
            if (lane == 0) sG0[j] = fmaxf(a + b_gcn[j], 0.0f);
        }
        __syncthreads();
        #pragma unroll
        for (int q = 0; q < 24; q++) {
            int r = q * 32 + wid;
            const float* wr = W_ih + r * 128;
            float a = 0.0f;
            #pragma unroll
            for (int kk = 0; kk < 4; kk++)
                a += wr[kk * 32 + lane] * sG0[kk * 32 + lane];
            #pragma unroll
            for (int o = 16; o; o >>= 1) a += __shfl_down_sync(0xffffffffu, a, o);
            if (lane == 0) sGi[r] = a + b_ih[r];
        }
        __syncthreads();
        if (t < 256) {
            float r_ = 1.0f / (1.0f + expf(-(sGi[t] + g_gh[t])));
            float z  = 1.0f / (1.0f + expf(-(sGi[256 + t] + g_gh[256 + t])));
            float nn = tanhf(sGi[512 + t] + r_ * g_gh[512 + t]);
            out[t] = (1.0f - z) * nn + z * h[t];
        }
        // reset device globals for the next (replayed) run
        for (int i = t; i < cnt + 2; i += B) g_nodecnt[i] = 0;
        if (t == 0) g_cnt = 0;
    }
}

// ---------------------------------------------------------------------------
extern "C" void kernel_launch(void* const* d_in, const int* in_sizes, int n_in,
                              void* d_out, int out_size) {
    const float* nf    = (const float*)d_in[0];
    // d_in[1] = edge_attr (unused by reference)
    const float* h     = (const float*)d_in[2];
    const float* W_enc = (const float*)d_in[3];
    const float* b_enc = (const float*)d_in[4];
    const float* W_gcn = (const float*)d_in[5];
    const float* b_gcn = (const float*)d_in[6];
    const float* W_ih  = (const float*)d_in[7];
    const float* W_hh  = (const float*)d_in[8];
    const float* b_ih  = (const float*)d_in[9];
    const float* b_hh  = (const float*)d_in[10];
    const unsigned* ei = (const unsigned*)d_in[11];
    int E = in_sizes[11] / 2;
    int N = in_sizes[0] / 64;
    float* out = (float*)d_out;

    int smem = (2 * N + 15) & ~15;
    if (smem < 8192) smem = 8192;                  // room for tail reuse arrays
    cudaFuncSetAttribute(k_fused, cudaFuncAttributeMaxDynamicSharedMemorySize, smem);

    k_fused<<<G, B, smem>>>(nf, h, W_enc, b_enc, W_gcn, b_gcn,
                            W_ih, W_hh, b_ih, b_hh, ei, E, N, out);
}